// round 15
// baseline (speedup 1.0000x reference)
#include <cuda_runtime.h>
#include <cuda_bf16.h>
#include <cstdint>

#define FDIM 128
#define MAXN 100000
#define MAXE 1600000
#define SEG 1024
#define MAXSEG 128
#define MAXTILES ((MAXN + 63) / 64)

// A-tile staging layout (global AND smem share it):
// per tile: 4 parts (ah, al, eh, el) x 64 rows x APAD bf16 elems.
#define APAD 136
#define WPAD 136
#define ROW_U2   34                   // uint2 (8B) per row = 272B
#define PART_U2  (64 * ROW_U2)        // 2176
#define TILE_U2  (4 * PART_U2)        // 8704  (69632 B per tile)
#define PAIR_U2  (2 * PART_U2)        // 4352  (34816 B per part-pair)
#define PAIR_GRAN (PAIR_U2 / 2)       // 2176 16B granules per pair

// ---------------------------------------------------------------------------
// Scratch
// ---------------------------------------------------------------------------
__device__ int   g_cnt[MAXN];     // zero at module load; re-zeroed by permute
__device__ int   g_off[MAXN + 1];
__device__ int   g_cur[MAXN];
__device__ int   g_bsum[MAXSEG];
__device__ int2  g_edge[MAXE];    // packed {src, val-bits}
__device__ uint2 g_A[(size_t)MAXTILES * TILE_U2];   // pre-split bf16 tiles

// ---------------------------------------------------------------------------
// Histogram of dst
// ---------------------------------------------------------------------------
__global__ void hist_kernel(const int* __restrict__ dst, int E) {
    int e = blockIdx.x * blockDim.x + threadIdx.x;
    if (e < E) atomicAdd(&g_cnt[dst[e]], 1);
}

// ---------------------------------------------------------------------------
// Scan stage 1: per-segment sums
// ---------------------------------------------------------------------------
__global__ void __launch_bounds__(256) scan1_kernel(int N) {
    __shared__ int ssum[256];
    int t = threadIdx.x;
    int base = blockIdx.x * SEG + t * 4;
    int s = 0;
#pragma unroll
    for (int j = 0; j < 4; ++j) {
        int idx = base + j;
        if (idx < N) s += g_cnt[idx];
    }
    ssum[t] = s;
    __syncthreads();
#pragma unroll
    for (int off = 128; off > 0; off >>= 1) {
        if (t < off) ssum[t] += ssum[t + off];
        __syncthreads();
    }
    if (t == 0) g_bsum[blockIdx.x] = ssum[0];
}

// ---------------------------------------------------------------------------
// Scan stage 3 (scan2 folded in): every block scans segment sums locally.
// ---------------------------------------------------------------------------
__global__ void __launch_bounds__(256) scan3_kernel(int N, int E, int nseg) {
    __shared__ int ssum[256];
    __shared__ int sbs[MAXSEG];
    int t = threadIdx.x;

    if (t < MAXSEG) sbs[t] = (t < nseg) ? g_bsum[t] : 0;
    __syncthreads();
#pragma unroll
    for (int off = 1; off < MAXSEG; off <<= 1) {
        int x = 0;
        if (t < MAXSEG && t >= off) x = sbs[t - off];
        __syncthreads();
        if (t < MAXSEG) sbs[t] += x;
        __syncthreads();
    }
    int blockPrefix = (blockIdx.x == 0) ? 0 : sbs[blockIdx.x - 1];

    int base = blockIdx.x * SEG + t * 4;
    int c[4];
    int tsum = 0;
#pragma unroll
    for (int j = 0; j < 4; ++j) {
        int idx = base + j;
        c[j] = (idx < N) ? g_cnt[idx] : 0;
        tsum += c[j];
    }
    ssum[t] = tsum;
    __syncthreads();
#pragma unroll
    for (int off = 1; off < 256; off <<= 1) {
        int x = (t >= off) ? ssum[t - off] : 0;
        __syncthreads();
        ssum[t] += x;
        __syncthreads();
    }
    int excl = ssum[t] - tsum;
    int pos = blockPrefix + excl;
#pragma unroll
    for (int j = 0; j < 4; ++j) {
        int idx = base + j;
        if (idx < N) {
            g_off[idx] = pos;
            g_cur[idx] = pos;
            pos += c[j];
        }
    }
    if (blockIdx.x == 0 && t == 0) g_off[N] = E;
}

// ---------------------------------------------------------------------------
// Permute edges into CSR order (packed int2); re-zero g_cnt for next call.
// ---------------------------------------------------------------------------
__global__ void permute_kernel(const int* __restrict__ src,
                               const int* __restrict__ dst,
                               const float* __restrict__ val, int E, int N) {
    int e = blockIdx.x * blockDim.x + threadIdx.x;
    if (e < N) g_cnt[e] = 0;
    if (e < E) {
        int d = dst[e];
        int p = atomicAdd(&g_cur[d], 1);
        g_edge[p] = make_int2(src[e], __float_as_int(val[e]));
    }
}

// ---------------------------------------------------------------------------
// bf16 pack helper: {lo, hi} fp32 -> bf16x2
// ---------------------------------------------------------------------------
__device__ __forceinline__ uint32_t pk2(float lo, float hi) {
    uint32_t r;
    asm("cvt.rn.bf16x2.f32 %0, %1, %2;" : "=r"(r) : "f"(hi), "f"(lo));
    return r;
}

// ---------------------------------------------------------------------------
// Gather + convert: one warp per node.
//   LE = sum_e val[e] * feats[src[e]]   (register accumulator)
//   a = LE + feats[node], e = LE * feats[node]
//   split a,e into bf16 hi/lo and store the node's row of the 4 tile parts.
// ---------------------------------------------------------------------------
__global__ void __launch_bounds__(256)
gather_kernel(const float* __restrict__ feats, int N) {
    int node = (blockIdx.x << 3) + (threadIdx.x >> 5);
    if (node >= N) return;
    int lane = threadIdx.x & 31;
    int start = g_off[node];
    int end = g_off[node + 1];

    float4 acc = make_float4(0.f, 0.f, 0.f, 0.f);
    for (int base = start; base < end; base += 32) {
        int n = end - base;
        if (n > 32) n = 32;
        int s = 0;
        float v = 0.f;
        if (lane < n) {
            int2 ev = g_edge[base + lane];
            s = ev.x;
            v = __int_as_float(ev.y);
        }
#pragma unroll 4
        for (int j = 0; j < n; ++j) {
            int sj = __shfl_sync(0xffffffff, s, j);
            float vj = __shfl_sync(0xffffffff, v, j);
            float4 f = *reinterpret_cast<const float4*>(
                &feats[(long long)sj * FDIM + lane * 4]);
            acc.x += vj * f.x;
            acc.y += vj * f.y;
            acc.z += vj * f.z;
            acc.w += vj * f.w;
        }
    }

    // Convert: a = LE + ft, e = LE * ft; split to bf16 hi/lo.
    float4 ft = *reinterpret_cast<const float4*>(
        &feats[(long long)node * FDIM + lane * 4]);
    float a0 = acc.x + ft.x, a1 = acc.y + ft.y;
    float a2 = acc.z + ft.z, a3 = acc.w + ft.w;
    float e0 = acc.x * ft.x, e1 = acc.y * ft.y;
    float e2 = acc.z * ft.z, e3 = acc.w * ft.w;

    uint32_t ah01 = pk2(a0, a1), ah23 = pk2(a2, a3);
    float ar0 = a0 - __uint_as_float(ah01 << 16);
    float ar1 = a1 - __uint_as_float(ah01 & 0xFFFF0000u);
    float ar2 = a2 - __uint_as_float(ah23 << 16);
    float ar3 = a3 - __uint_as_float(ah23 & 0xFFFF0000u);
    uint2 ahv = make_uint2(ah01, ah23);
    uint2 alv = make_uint2(pk2(ar0, ar1), pk2(ar2, ar3));

    uint32_t eh01 = pk2(e0, e1), eh23 = pk2(e2, e3);
    float er0 = e0 - __uint_as_float(eh01 << 16);
    float er1 = e1 - __uint_as_float(eh01 & 0xFFFF0000u);
    float er2 = e2 - __uint_as_float(eh23 << 16);
    float er3 = e3 - __uint_as_float(eh23 & 0xFFFF0000u);
    uint2 ehv = make_uint2(eh01, eh23);
    uint2 elv = make_uint2(pk2(er0, er1), pk2(er2, er3));

    // Store the node's row into its tile's 4 parts (coalesced 256B per part).
    size_t base = (size_t)(node >> 6) * TILE_U2 + (size_t)(node & 63) * ROW_U2 + lane;
    g_A[base + 0 * PART_U2] = ahv;
    g_A[base + 1 * PART_U2] = alv;
    g_A[base + 2 * PART_U2] = ehv;
    g_A[base + 3 * PART_U2] = elv;
}

// ---------------------------------------------------------------------------
// HMMA helper
// ---------------------------------------------------------------------------
__device__ __forceinline__ void mma16816(float* c, uint32_t a0, uint32_t a1,
                                         uint32_t a2, uint32_t a3,
                                         uint32_t b0, uint32_t b1) {
    asm volatile(
        "mma.sync.aligned.m16n8k16.row.col.f32.bf16.bf16.f32 "
        "{%0,%1,%2,%3}, {%4,%5,%6,%7}, {%8,%9}, {%0,%1,%2,%3};"
        : "+f"(c[0]), "+f"(c[1]), "+f"(c[2]), "+f"(c[3])
        : "r"(a0), "r"(a1), "r"(a2), "r"(a3), "r"(b0), "r"(b1));
}

// ---------------------------------------------------------------------------
// GEMM: tiles arrive pre-converted. Part-pair staged cp.async pipeline:
// ph0 reads {ah,al}, ph1 reads {eh,el}; each pair's copy is issued one
// phase ahead so its latency hides under a full MMA phase, not the epilogue.
// Persistent, 1 CTA/SM, 256 threads (8 warps: 2x4 m/n grid), 64-row tiles.
// ---------------------------------------------------------------------------
#define OFF_A    0
#define OFF_W1H  69632
#define OFF_W1L  (OFF_W1H + 128 * WPAD * 2)
#define OFF_W2H  (OFF_W1L + 128 * WPAD * 2)
#define OFF_W2L  (OFF_W2H + 128 * WPAD * 2)
#define OFF_BIAS (OFF_W2L + 128 * WPAD * 2)
#define SMEM_TOTAL_MM (OFF_BIAS + 128 * 4)    // 209,920 B

#define CP_ASYNC16(sa, gp) \
    asm volatile("cp.async.cg.shared.global [%0], [%1], 16;" \
                 :: "r"(sa), "l"(gp))
#define CP_COMMIT() asm volatile("cp.async.commit_group;")
#define CP_WAIT1()  asm volatile("cp.async.wait_group 1;")
#define CP_WAIT0()  asm volatile("cp.async.wait_group 0;")

// Copy one part-pair (2176 granules of 16B) of tile T, pair P (0 or 1).
#define COPY_PAIR(T, P) do {                                                  \
        const uint2* gsrc_ = g_A + (size_t)(T) * TILE_U2 + (P) * PAIR_U2;     \
        uint32_t sdst_ = smem_u32 + OFF_A + (P) * (PAIR_U2 * 8);              \
        _Pragma("unroll")                                                     \
        for (int i_ = 0; i_ < 9; ++i_) {                                      \
            int g_ = tid + i_ * 256;                                          \
            if (g_ < PAIR_GRAN)                                               \
                CP_ASYNC16(sdst_ + g_ * 16, gsrc_ + (size_t)g_ * 2);          \
        }                                                                     \
        CP_COMMIT();                                                          \
    } while (0)

__global__ void __launch_bounds__(256, 1)
gemm_mm_kernel(const float* __restrict__ W1, const float* __restrict__ b1,
               const float* __restrict__ W2, const float* __restrict__ b2,
               float* __restrict__ out, int N, int nTiles) {
    extern __shared__ char smem[];
    uint32_t smem_u32;
    asm("{ .reg .u64 t; cvta.to.shared.u64 t, %1; cvt.u32.u64 %0, t; }"
        : "=r"(smem_u32) : "l"(smem));

    int tid = threadIdx.x;
    int wid = tid >> 5;
    int lane = tid & 31;
    int wm = wid & 1;        // 0..1 : 32-row slice
    int wn = wid >> 1;       // 0..3 : 32-col slice
    int grp = lane >> 2;     // 0..7
    int quad = lane & 3;     // 0..3

    // ---- one-time: split W1/W2 into bf16 hi/lo in smem; bias ----
    for (int i = tid; i < FDIM * FDIM; i += 256) {
        int n = i >> 7;
        int k = i & 127;
        float w1 = W1[i];
        float w2 = W2[i];
        uint32_t h1 = pk2(w1, 0.f) & 0xFFFFu;
        uint32_t h2 = pk2(w2, 0.f) & 0xFFFFu;
        float r1 = w1 - __uint_as_float(h1 << 16);
        float r2 = w2 - __uint_as_float(h2 << 16);
        uint32_t l1 = pk2(r1, 0.f) & 0xFFFFu;
        uint32_t l2 = pk2(r2, 0.f) & 0xFFFFu;
        size_t o = (size_t)(n * WPAD + k) * 2;
        *(uint16_t*)(smem + OFF_W1H + o) = (uint16_t)h1;
        *(uint16_t*)(smem + OFF_W1L + o) = (uint16_t)l1;
        *(uint16_t*)(smem + OFF_W2H + o) = (uint16_t)h2;
        *(uint16_t*)(smem + OFF_W2L + o) = (uint16_t)l2;
    }
    for (int i = tid; i < FDIM; i += 256)
        *(float*)(smem + OFF_BIAS + i * 4) = b1[i] + b2[i];
    __syncthreads();

    float bv[4][2];
#pragma unroll
    for (int j = 0; j < 4; ++j) {
        int col = wn * 32 + j * 8 + quad * 2;
        bv[j][0] = *(float*)(smem + OFF_BIAS + col * 4);
        bv[j][1] = *(float*)(smem + OFF_BIAS + (col + 1) * 4);
    }

    // ---- prologue: both part-pairs of the first tile in flight ----
    if (blockIdx.x < nTiles) {
        COPY_PAIR((int)blockIdx.x, 0);
        COPY_PAIR((int)blockIdx.x, 1);
    }

    for (int tile = blockIdx.x; tile < nTiles; tile += gridDim.x) {
        int row0 = tile << 6;
        int nxt = tile + (int)gridDim.x;
        bool has_next = nxt < nTiles;

        float acc[2][4][4];
#pragma unroll
        for (int mt = 0; mt < 2; ++mt)
#pragma unroll
            for (int nt = 0; nt < 4; ++nt)
#pragma unroll
                for (int f = 0; f < 4; ++f) acc[mt][nt][f] = 0.f;

        const int aoffH[2] = {OFF_A, OFF_A + 2 * PART_U2 * 8};
        const int aoffL[2] = {OFF_A + 1 * PART_U2 * 8, OFF_A + 3 * PART_U2 * 8};
        const int woffH[2] = {OFF_W1H, OFF_W2H};
        const int woffL[2] = {OFF_W1L, OFF_W2L};

#pragma unroll
        for (int ph = 0; ph < 2; ++ph) {
            // Wait for this phase's part-pair. Entering ph0: pending =
            // {p0(t), p1(t)} -> wait 1 releases p0. Entering ph1: pending =
            // {p1(t), p0(nxt)} (or {p1(t)}) -> wait handled below.
            if (ph == 0) {
                CP_WAIT1();
            } else {
                if (has_next) CP_WAIT1(); else CP_WAIT0();
            }
            __syncthreads();

            const char* sAH = smem + aoffH[ph];
            const char* sAL = smem + aoffL[ph];
            const char* sWH = smem + woffH[ph];
            const char* sWL = smem + woffL[ph];
#pragma unroll
            for (int ks = 0; ks < 8; ++ks) {
                int kb = ks * 16 + quad * 2;
                uint32_t bh[4][2], bl[4][2];
#pragma unroll
                for (int nt = 0; nt < 4; ++nt) {
                    int n = wn * 32 + nt * 8 + grp;
                    size_t o0 = (size_t)(n * WPAD + kb) * 2;
                    size_t o1 = (size_t)(n * WPAD + kb + 8) * 2;
                    bh[nt][0] = *(const uint32_t*)(sWH + o0);
                    bh[nt][1] = *(const uint32_t*)(sWH + o1);
                    bl[nt][0] = *(const uint32_t*)(sWL + o0);
                    bl[nt][1] = *(const uint32_t*)(sWL + o1);
                }
#pragma unroll
                for (int mt = 0; mt < 2; ++mt) {
                    int rA = wm * 32 + mt * 16 + grp;
                    size_t o0 = (size_t)(rA * APAD + kb) * 2;
                    size_t o1 = (size_t)((rA + 8) * APAD + kb) * 2;
                    size_t o2 = (size_t)(rA * APAD + kb + 8) * 2;
                    size_t o3 = (size_t)((rA + 8) * APAD + kb + 8) * 2;
                    uint32_t ah0 = *(const uint32_t*)(sAH + o0);
                    uint32_t ah1 = *(const uint32_t*)(sAH + o1);
                    uint32_t ah2 = *(const uint32_t*)(sAH + o2);
                    uint32_t ah3 = *(const uint32_t*)(sAH + o3);
                    uint32_t al0 = *(const uint32_t*)(sAL + o0);
                    uint32_t al1 = *(const uint32_t*)(sAL + o1);
                    uint32_t al2 = *(const uint32_t*)(sAL + o2);
                    uint32_t al3 = *(const uint32_t*)(sAL + o3);
#pragma unroll
                    for (int nt = 0; nt < 4; ++nt) {
                        mma16816(acc[mt][nt], ah0, ah1, ah2, ah3, bh[nt][0], bh[nt][1]);
                        mma16816(acc[mt][nt], al0, al1, al2, al3, bh[nt][0], bh[nt][1]);
                        mma16816(acc[mt][nt], ah0, ah1, ah2, ah3, bl[nt][0], bl[nt][1]);
                    }
                }
            }

            // All warps done reading this phase's pair; refill it for nxt.
            __syncthreads();
            if (has_next) COPY_PAIR(nxt, ph);
        }

        // ---- epilogue: acc + bias -> out ----
#pragma unroll
        for (int mt = 0; mt < 2; ++mt) {
            int r_lo = row0 + wm * 32 + mt * 16 + grp;
            int r_hi = r_lo + 8;
#pragma unroll
            for (int nt = 0; nt < 4; ++nt) {
                int col = wn * 32 + nt * 8 + quad * 2;
                if (r_lo < N) {
                    float2 o;
                    o.x = acc[mt][nt][0] + bv[nt][0];
                    o.y = acc[mt][nt][1] + bv[nt][1];
                    *(float2*)&out[(size_t)r_lo * FDIM + col] = o;
                }
                if (r_hi < N) {
                    float2 o;
                    o.x = acc[mt][nt][2] + bv[nt][0];
                    o.y = acc[mt][nt][3] + bv[nt][1];
                    *(float2*)&out[(size_t)r_hi * FDIM + col] = o;
                }
            }
        }
    }
}

// ---------------------------------------------------------------------------
extern "C" void kernel_launch(void* const* d_in, const int* in_sizes, int n_in,
                              void* d_out, int out_size) {
    const int*   src   = (const int*)d_in[0];
    const int*   dst   = (const int*)d_in[1];
    const float* val   = (const float*)d_in[2];
    const float* feats = (const float*)d_in[3];
    const float* W1    = (const float*)d_in[4];
    const float* b1    = (const float*)d_in[5];
    const float* W2    = (const float*)d_in[6];
    const float* b2    = (const float*)d_in[7];
    float* out = (float*)d_out;

    int E = in_sizes[0];
    int N = in_sizes[3] / FDIM;
    int nseg = (N + SEG - 1) / SEG;
    int nTiles = (N + 63) / 64;

    cudaFuncSetAttribute(gemm_mm_kernel,
                         cudaFuncAttributeMaxDynamicSharedMemorySize,
                         SMEM_TOTAL_MM);

    hist_kernel<<<(E + 255) / 256, 256>>>(dst, E);
    scan1_kernel<<<nseg, 256>>>(N);
    scan3_kernel<<<nseg, 256>>>(N, E, nseg);
    permute_kernel<<<(E + 255) / 256, 256>>>(src, dst, val, E, N);
    gather_kernel<<<(N + 7) / 8, 256>>>(feats, N);

    int grid = nTiles < 148 ? nTiles : 148;
    gemm_mm_kernel<<<grid, 256, SMEM_TOTAL_MM>>>(W1, b1, W2, b2, out,
                                                 N, nTiles);
}

// round 16
// speedup vs baseline: 1.0011x; 1.0011x over previous
#include <cuda_runtime.h>
#include <cuda_bf16.h>
#include <cstdint>

#define FDIM 128
#define MAXN 100000
#define MAXE 1600000
#define SEG 1024
#define MAXSEG 128
#define MAXTILES ((MAXN + 63) / 64)

// A-tile staging layout (global AND smem share it):
// per tile: 4 parts (ah, al, eh, el) x 64 rows x APAD bf16 elems.
#define APAD 136
#define WPAD 136
#define ROW_U2   34                   // uint2 (8B) per row = 272B
#define PART_U2  (64 * ROW_U2)        // 2176
#define TILE_U2  (4 * PART_U2)        // 8704  (69632 B per tile)
#define PAIR_U2  (2 * PART_U2)        // 4352  (34816 B per part-pair)
#define PAIR_GRAN (PAIR_U2 / 2)       // 2176 16B granules per pair

// ---------------------------------------------------------------------------
// Scratch
// ---------------------------------------------------------------------------
__device__ int   g_cnt[MAXN];     // zero at module load; re-zeroed by permute
__device__ int   g_off[MAXN + 1];
__device__ int   g_cur[MAXN];
__device__ int   g_bsum[MAXSEG];
__device__ int2  g_edge[MAXE];    // packed {src, val-bits}
__device__ uint2 g_A[(size_t)MAXTILES * TILE_U2];   // pre-split bf16 tiles

// ---------------------------------------------------------------------------
// Histogram of dst: 4 edges per thread (vector load + 4 independent atomics)
// ---------------------------------------------------------------------------
__global__ void hist_kernel(const int* __restrict__ dst, int E) {
    int t = blockIdx.x * blockDim.x + threadIdx.x;
    int base = t * 4;
    if (base + 3 < E) {
        int4 d4 = *(const int4*)&dst[base];
        atomicAdd(&g_cnt[d4.x], 1);
        atomicAdd(&g_cnt[d4.y], 1);
        atomicAdd(&g_cnt[d4.z], 1);
        atomicAdd(&g_cnt[d4.w], 1);
    } else {
        for (int e = base; e < E; ++e) atomicAdd(&g_cnt[dst[e]], 1);
    }
}

// ---------------------------------------------------------------------------
// Scan stage 1: per-segment sums
// ---------------------------------------------------------------------------
__global__ void __launch_bounds__(256) scan1_kernel(int N) {
    __shared__ int ssum[256];
    int t = threadIdx.x;
    int base = blockIdx.x * SEG + t * 4;
    int s = 0;
#pragma unroll
    for (int j = 0; j < 4; ++j) {
        int idx = base + j;
        if (idx < N) s += g_cnt[idx];
    }
    ssum[t] = s;
    __syncthreads();
#pragma unroll
    for (int off = 128; off > 0; off >>= 1) {
        if (t < off) ssum[t] += ssum[t + off];
        __syncthreads();
    }
    if (t == 0) g_bsum[blockIdx.x] = ssum[0];
}

// ---------------------------------------------------------------------------
// Scan stage 3 (scan2 folded in): every block scans segment sums locally.
// ---------------------------------------------------------------------------
__global__ void __launch_bounds__(256) scan3_kernel(int N, int E, int nseg) {
    __shared__ int ssum[256];
    __shared__ int sbs[MAXSEG];
    int t = threadIdx.x;

    if (t < MAXSEG) sbs[t] = (t < nseg) ? g_bsum[t] : 0;
    __syncthreads();
#pragma unroll
    for (int off = 1; off < MAXSEG; off <<= 1) {
        int x = 0;
        if (t < MAXSEG && t >= off) x = sbs[t - off];
        __syncthreads();
        if (t < MAXSEG) sbs[t] += x;
        __syncthreads();
    }
    int blockPrefix = (blockIdx.x == 0) ? 0 : sbs[blockIdx.x - 1];

    int base = blockIdx.x * SEG + t * 4;
    int c[4];
    int tsum = 0;
#pragma unroll
    for (int j = 0; j < 4; ++j) {
        int idx = base + j;
        c[j] = (idx < N) ? g_cnt[idx] : 0;
        tsum += c[j];
    }
    ssum[t] = tsum;
    __syncthreads();
#pragma unroll
    for (int off = 1; off < 256; off <<= 1) {
        int x = (t >= off) ? ssum[t - off] : 0;
        __syncthreads();
        ssum[t] += x;
        __syncthreads();
    }
    int excl = ssum[t] - tsum;
    int pos = blockPrefix + excl;
#pragma unroll
    for (int j = 0; j < 4; ++j) {
        int idx = base + j;
        if (idx < N) {
            g_off[idx] = pos;
            g_cur[idx] = pos;
            pos += c[j];
        }
    }
    if (blockIdx.x == 0 && t == 0) g_off[N] = E;
}

// ---------------------------------------------------------------------------
// Permute edges into CSR order (packed int2): 4 edges per thread so the
// LDG->ATOMG->STG chains overlap (MLP=4). Also re-zeroes g_cnt.
// ---------------------------------------------------------------------------
__global__ void permute_kernel(const int* __restrict__ src,
                               const int* __restrict__ dst,
                               const float* __restrict__ val, int E, int N) {
    int t = blockIdx.x * blockDim.x + threadIdx.x;
    if (t < N) g_cnt[t] = 0;

    int base = t * 4;
    if (base + 3 < E) {
        int4   s4 = *(const int4*)&src[base];
        int4   d4 = *(const int4*)&dst[base];
        float4 v4 = *(const float4*)&val[base];
        int p0 = atomicAdd(&g_cur[d4.x], 1);
        int p1 = atomicAdd(&g_cur[d4.y], 1);
        int p2 = atomicAdd(&g_cur[d4.z], 1);
        int p3 = atomicAdd(&g_cur[d4.w], 1);
        g_edge[p0] = make_int2(s4.x, __float_as_int(v4.x));
        g_edge[p1] = make_int2(s4.y, __float_as_int(v4.y));
        g_edge[p2] = make_int2(s4.z, __float_as_int(v4.z));
        g_edge[p3] = make_int2(s4.w, __float_as_int(v4.w));
    } else {
        for (int e = base; e < E; ++e) {
            int d = dst[e];
            int p = atomicAdd(&g_cur[d], 1);
            g_edge[p] = make_int2(src[e], __float_as_int(val[e]));
        }
    }
}

// ---------------------------------------------------------------------------
// bf16 pack helper: {lo, hi} fp32 -> bf16x2
// ---------------------------------------------------------------------------
__device__ __forceinline__ uint32_t pk2(float lo, float hi) {
    uint32_t r;
    asm("cvt.rn.bf16x2.f32 %0, %1, %2;" : "=r"(r) : "f"(hi), "f"(lo));
    return r;
}

// ---------------------------------------------------------------------------
// Gather + convert: one warp per node.
//   LE = sum_e val[e] * feats[src[e]]   (register accumulator)
//   a = LE + feats[node], e = LE * feats[node]
//   split a,e into bf16 hi/lo and store the node's row of the 4 tile parts.
// ---------------------------------------------------------------------------
__global__ void __launch_bounds__(256)
gather_kernel(const float* __restrict__ feats, int N) {
    int node = (blockIdx.x << 3) + (threadIdx.x >> 5);
    if (node >= N) return;
    int lane = threadIdx.x & 31;
    int start = g_off[node];
    int end = g_off[node + 1];

    float4 acc = make_float4(0.f, 0.f, 0.f, 0.f);
    for (int base = start; base < end; base += 32) {
        int n = end - base;
        if (n > 32) n = 32;
        int s = 0;
        float v = 0.f;
        if (lane < n) {
            int2 ev = g_edge[base + lane];
            s = ev.x;
            v = __int_as_float(ev.y);
        }
#pragma unroll 4
        for (int j = 0; j < n; ++j) {
            int sj = __shfl_sync(0xffffffff, s, j);
            float vj = __shfl_sync(0xffffffff, v, j);
            float4 f = *reinterpret_cast<const float4*>(
                &feats[(long long)sj * FDIM + lane * 4]);
            acc.x += vj * f.x;
            acc.y += vj * f.y;
            acc.z += vj * f.z;
            acc.w += vj * f.w;
        }
    }

    // Convert: a = LE + ft, e = LE * ft; split to bf16 hi/lo.
    float4 ft = *reinterpret_cast<const float4*>(
        &feats[(long long)node * FDIM + lane * 4]);
    float a0 = acc.x + ft.x, a1 = acc.y + ft.y;
    float a2 = acc.z + ft.z, a3 = acc.w + ft.w;
    float e0 = acc.x * ft.x, e1 = acc.y * ft.y;
    float e2 = acc.z * ft.z, e3 = acc.w * ft.w;

    uint32_t ah01 = pk2(a0, a1), ah23 = pk2(a2, a3);
    float ar0 = a0 - __uint_as_float(ah01 << 16);
    float ar1 = a1 - __uint_as_float(ah01 & 0xFFFF0000u);
    float ar2 = a2 - __uint_as_float(ah23 << 16);
    float ar3 = a3 - __uint_as_float(ah23 & 0xFFFF0000u);
    uint2 ahv = make_uint2(ah01, ah23);
    uint2 alv = make_uint2(pk2(ar0, ar1), pk2(ar2, ar3));

    uint32_t eh01 = pk2(e0, e1), eh23 = pk2(e2, e3);
    float er0 = e0 - __uint_as_float(eh01 << 16);
    float er1 = e1 - __uint_as_float(eh01 & 0xFFFF0000u);
    float er2 = e2 - __uint_as_float(eh23 << 16);
    float er3 = e3 - __uint_as_float(eh23 & 0xFFFF0000u);
    uint2 ehv = make_uint2(eh01, eh23);
    uint2 elv = make_uint2(pk2(er0, er1), pk2(er2, er3));

    // Store the node's row into its tile's 4 parts (coalesced 256B per part).
    size_t base = (size_t)(node >> 6) * TILE_U2 + (size_t)(node & 63) * ROW_U2 + lane;
    g_A[base + 0 * PART_U2] = ahv;
    g_A[base + 1 * PART_U2] = alv;
    g_A[base + 2 * PART_U2] = ehv;
    g_A[base + 3 * PART_U2] = elv;
}

// ---------------------------------------------------------------------------
// HMMA helper
// ---------------------------------------------------------------------------
__device__ __forceinline__ void mma16816(float* c, uint32_t a0, uint32_t a1,
                                         uint32_t a2, uint32_t a3,
                                         uint32_t b0, uint32_t b1) {
    asm volatile(
        "mma.sync.aligned.m16n8k16.row.col.f32.bf16.bf16.f32 "
        "{%0,%1,%2,%3}, {%4,%5,%6,%7}, {%8,%9}, {%0,%1,%2,%3};"
        : "+f"(c[0]), "+f"(c[1]), "+f"(c[2]), "+f"(c[3])
        : "r"(a0), "r"(a1), "r"(a2), "r"(a3), "r"(b0), "r"(b1));
}

// ---------------------------------------------------------------------------
// GEMM: tiles arrive pre-converted. Part-pair staged cp.async pipeline:
// ph0 reads {ah,al}, ph1 reads {eh,el}; each pair's copy is issued one
// phase ahead so its latency hides under a full MMA phase.
// Persistent, 1 CTA/SM, 256 threads (8 warps: 2x4 m/n grid), 64-row tiles.
// ---------------------------------------------------------------------------
#define OFF_A    0
#define OFF_W1H  69632
#define OFF_W1L  (OFF_W1H + 128 * WPAD * 2)
#define OFF_W2H  (OFF_W1L + 128 * WPAD * 2)
#define OFF_W2L  (OFF_W2H + 128 * WPAD * 2)
#define OFF_BIAS (OFF_W2L + 128 * WPAD * 2)
#define SMEM_TOTAL_MM (OFF_BIAS + 128 * 4)    // 209,920 B

#define CP_ASYNC16(sa, gp) \
    asm volatile("cp.async.cg.shared.global [%0], [%1], 16;" \
                 :: "r"(sa), "l"(gp))
#define CP_COMMIT() asm volatile("cp.async.commit_group;")
#define CP_WAIT1()  asm volatile("cp.async.wait_group 1;")
#define CP_WAIT0()  asm volatile("cp.async.wait_group 0;")

// Copy one part-pair (2176 granules of 16B) of tile T, pair P (0 or 1).
#define COPY_PAIR(T, P) do {                                                  \
        const uint2* gsrc_ = g_A + (size_t)(T) * TILE_U2 + (P) * PAIR_U2;     \
        uint32_t sdst_ = smem_u32 + OFF_A + (P) * (PAIR_U2 * 8);              \
        _Pragma("unroll")                                                     \
        for (int i_ = 0; i_ < 9; ++i_) {                                      \
            int g_ = tid + i_ * 256;                                          \
            if (g_ < PAIR_GRAN)                                               \
                CP_ASYNC16(sdst_ + g_ * 16, gsrc_ + (size_t)g_ * 2);          \
        }                                                                     \
        CP_COMMIT();                                                          \
    } while (0)

__global__ void __launch_bounds__(256, 1)
gemm_mm_kernel(const float* __restrict__ W1, const float* __restrict__ b1,
               const float* __restrict__ W2, const float* __restrict__ b2,
               float* __restrict__ out, int N, int nTiles) {
    extern __shared__ char smem[];
    uint32_t smem_u32;
    asm("{ .reg .u64 t; cvta.to.shared.u64 t, %1; cvt.u32.u64 %0, t; }"
        : "=r"(smem_u32) : "l"(smem));

    int tid = threadIdx.x;
    int wid = tid >> 5;
    int lane = tid & 31;
    int wm = wid & 1;        // 0..1 : 32-row slice
    int wn = wid >> 1;       // 0..3 : 32-col slice
    int grp = lane >> 2;     // 0..7
    int quad = lane & 3;     // 0..3

    // ---- one-time: split W1/W2 into bf16 hi/lo in smem; bias ----
    for (int i = tid; i < FDIM * FDIM; i += 256) {
        int n = i >> 7;
        int k = i & 127;
        float w1 = W1[i];
        float w2 = W2[i];
        uint32_t h1 = pk2(w1, 0.f) & 0xFFFFu;
        uint32_t h2 = pk2(w2, 0.f) & 0xFFFFu;
        float r1 = w1 - __uint_as_float(h1 << 16);
        float r2 = w2 - __uint_as_float(h2 << 16);
        uint32_t l1 = pk2(r1, 0.f) & 0xFFFFu;
        uint32_t l2 = pk2(r2, 0.f) & 0xFFFFu;
        size_t o = (size_t)(n * WPAD + k) * 2;
        *(uint16_t*)(smem + OFF_W1H + o) = (uint16_t)h1;
        *(uint16_t*)(smem + OFF_W1L + o) = (uint16_t)l1;
        *(uint16_t*)(smem + OFF_W2H + o) = (uint16_t)h2;
        *(uint16_t*)(smem + OFF_W2L + o) = (uint16_t)l2;
    }
    for (int i = tid; i < FDIM; i += 256)
        *(float*)(smem + OFF_BIAS + i * 4) = b1[i] + b2[i];
    __syncthreads();

    float bv[4][2];
#pragma unroll
    for (int j = 0; j < 4; ++j) {
        int col = wn * 32 + j * 8 + quad * 2;
        bv[j][0] = *(float*)(smem + OFF_BIAS + col * 4);
        bv[j][1] = *(float*)(smem + OFF_BIAS + (col + 1) * 4);
    }

    // ---- prologue: both part-pairs of the first tile in flight ----
    if (blockIdx.x < nTiles) {
        COPY_PAIR((int)blockIdx.x, 0);
        COPY_PAIR((int)blockIdx.x, 1);
    }

    for (int tile = blockIdx.x; tile < nTiles; tile += gridDim.x) {
        int row0 = tile << 6;
        int nxt = tile + (int)gridDim.x;
        bool has_next = nxt < nTiles;

        float acc[2][4][4];
#pragma unroll
        for (int mt = 0; mt < 2; ++mt)
#pragma unroll
            for (int nt = 0; nt < 4; ++nt)
#pragma unroll
                for (int f = 0; f < 4; ++f) acc[mt][nt][f] = 0.f;

        const int aoffH[2] = {OFF_A, OFF_A + 2 * PART_U2 * 8};
        const int aoffL[2] = {OFF_A + 1 * PART_U2 * 8, OFF_A + 3 * PART_U2 * 8};
        const int woffH[2] = {OFF_W1H, OFF_W2H};
        const int woffL[2] = {OFF_W1L, OFF_W2L};

#pragma unroll
        for (int ph = 0; ph < 2; ++ph) {
            if (ph == 0) {
                CP_WAIT1();
            } else {
                if (has_next) CP_WAIT1(); else CP_WAIT0();
            }
            __syncthreads();

            const char* sAH = smem + aoffH[ph];
            const char* sAL = smem + aoffL[ph];
            const char* sWH = smem + woffH[ph];
            const char* sWL = smem + woffL[ph];
#pragma unroll
            for (int ks = 0; ks < 8; ++ks) {
                int kb = ks * 16 + quad * 2;
                uint32_t bh[4][2], bl[4][2];
#pragma unroll
                for (int nt = 0; nt < 4; ++nt) {
                    int n = wn * 32 + nt * 8 + grp;
                    size_t o0 = (size_t)(n * WPAD + kb) * 2;
                    size_t o1 = (size_t)(n * WPAD + kb + 8) * 2;
                    bh[nt][0] = *(const uint32_t*)(sWH + o0);
                    bh[nt][1] = *(const uint32_t*)(sWH + o1);
                    bl[nt][0] = *(const uint32_t*)(sWL + o0);
                    bl[nt][1] = *(const uint32_t*)(sWL + o1);
                }
#pragma unroll
                for (int mt = 0; mt < 2; ++mt) {
                    int rA = wm * 32 + mt * 16 + grp;
                    size_t o0 = (size_t)(rA * APAD + kb) * 2;
                    size_t o1 = (size_t)((rA + 8) * APAD + kb) * 2;
                    size_t o2 = (size_t)(rA * APAD + kb + 8) * 2;
                    size_t o3 = (size_t)((rA + 8) * APAD + kb + 8) * 2;
                    uint32_t ah0 = *(const uint32_t*)(sAH + o0);
                    uint32_t ah1 = *(const uint32_t*)(sAH + o1);
                    uint32_t ah2 = *(const uint32_t*)(sAH + o2);
                    uint32_t ah3 = *(const uint32_t*)(sAH + o3);
                    uint32_t al0 = *(const uint32_t*)(sAL + o0);
                    uint32_t al1 = *(const uint32_t*)(sAL + o1);
                    uint32_t al2 = *(const uint32_t*)(sAL + o2);
                    uint32_t al3 = *(const uint32_t*)(sAL + o3);
#pragma unroll
                    for (int nt = 0; nt < 4; ++nt) {
                        mma16816(acc[mt][nt], ah0, ah1, ah2, ah3, bh[nt][0], bh[nt][1]);
                        mma16816(acc[mt][nt], al0, al1, al2, al3, bh[nt][0], bh[nt][1]);
                        mma16816(acc[mt][nt], ah0, ah1, ah2, ah3, bl[nt][0], bl[nt][1]);
                    }
                }
            }

            __syncthreads();
            if (has_next) COPY_PAIR(nxt, ph);
        }

        // ---- epilogue: acc + bias -> out ----
#pragma unroll
        for (int mt = 0; mt < 2; ++mt) {
            int r_lo = row0 + wm * 32 + mt * 16 + grp;
            int r_hi = r_lo + 8;
#pragma unroll
            for (int nt = 0; nt < 4; ++nt) {
                int col = wn * 32 + nt * 8 + quad * 2;
                if (r_lo < N) {
                    float2 o;
                    o.x = acc[mt][nt][0] + bv[nt][0];
                    o.y = acc[mt][nt][1] + bv[nt][1];
                    *(float2*)&out[(size_t)r_lo * FDIM + col] = o;
                }
                if (r_hi < N) {
                    float2 o;
                    o.x = acc[mt][nt][2] + bv[nt][0];
                    o.y = acc[mt][nt][3] + bv[nt][1];
                    *(float2*)&out[(size_t)r_hi * FDIM + col] = o;
                }
            }
        }
    }
}

// ---------------------------------------------------------------------------
extern "C" void kernel_launch(void* const* d_in, const int* in_sizes, int n_in,
                              void* d_out, int out_size) {
    const int*   src   = (const int*)d_in[0];
    const int*   dst   = (const int*)d_in[1];
    const float* val   = (const float*)d_in[2];
    const float* feats = (const float*)d_in[3];
    const float* W1    = (const float*)d_in[4];
    const float* b1    = (const float*)d_in[5];
    const float* W2    = (const float*)d_in[6];
    const float* b2    = (const float*)d_in[7];
    float* out = (float*)d_out;

    int E = in_sizes[0];
    int N = in_sizes[3] / FDIM;
    int nseg = (N + SEG - 1) / SEG;
    int nTiles = (N + 63) / 64;

    cudaFuncSetAttribute(gemm_mm_kernel,
                         cudaFuncAttributeMaxDynamicSharedMemorySize,
                         SMEM_TOTAL_MM);

    int e4 = (E + 3) / 4;   // threads for 4-edge kernels
    hist_kernel<<<(e4 + 255) / 256, 256>>>(dst, E);
    scan1_kernel<<<nseg, 256>>>(N);
    scan3_kernel<<<nseg, 256>>>(N, E, nseg);
    {
        // permute also zeroes g_cnt[0..N): need max(e4, N) threads
        int nthr = e4 > N ? e4 : N;
        permute_kernel<<<(nthr + 255) / 256, 256>>>(src, dst, val, E, N);
    }
    gather_kernel<<<(N + 7) / 8, 256>>>(feats, N);

    int grid = nTiles < 148 ? nTiles : 148;
    gemm_mm_kernel<<<grid, 256, SMEM_TOTAL_MM>>>(W1, b1, W2, b2, out,
                                                 N, nTiles);
}

// round 17
// speedup vs baseline: 1.0177x; 1.0166x over previous
#include <cuda_runtime.h>
#include <cuda_bf16.h>
#include <cstdint>

#define FDIM 128
#define MAXN 100000
#define MAXE 1600000
#define SEG 1024
#define MAXSEG 128
#define MAXTILES ((MAXN + 63) / 64)

// A-tile staging layout (global AND smem share it):
// per tile: 4 parts (ah, al, eh, el) x 64 rows x APAD bf16 elems.
#define APAD 136
#define WPAD 136
#define ROW_U2   34                   // uint2 (8B) per row = 272B
#define PART_U2  (64 * ROW_U2)        // 2176
#define TILE_U2  (4 * PART_U2)        // 8704  (69632 B per tile)
#define PAIR_U2  (2 * PART_U2)        // 4352  (34816 B per part-pair)
#define PAIR_GRAN (PAIR_U2 / 2)       // 2176 16B granules per pair

// ---------------------------------------------------------------------------
// Scratch
// ---------------------------------------------------------------------------
__device__ int   g_cnt[MAXN];     // zero at module load; re-zeroed by permute
__device__ int   g_off[MAXN + 1];
__device__ int   g_bsum[MAXSEG];
__device__ int   g_rank[MAXE];    // within-node rank of each edge (from hist)
__device__ int2  g_edge[MAXE];    // packed {src, val-bits} in CSR order
__device__ uint2 g_A[(size_t)MAXTILES * TILE_U2];   // pre-split bf16 tiles

// ---------------------------------------------------------------------------
// Histogram of dst + rank assignment: the atomic's return value IS the
// within-node rank; store it coalesced so permute needs no atomics.
// ---------------------------------------------------------------------------
__global__ void hist_kernel(const int* __restrict__ dst, int E) {
    int t = blockIdx.x * blockDim.x + threadIdx.x;
    int base = t * 4;
    if (base + 3 < E) {
        int4 d4 = *(const int4*)&dst[base];
        int4 r4;
        r4.x = atomicAdd(&g_cnt[d4.x], 1);
        r4.y = atomicAdd(&g_cnt[d4.y], 1);
        r4.z = atomicAdd(&g_cnt[d4.z], 1);
        r4.w = atomicAdd(&g_cnt[d4.w], 1);
        *(int4*)&g_rank[base] = r4;
    } else {
        for (int e = base; e < E; ++e)
            g_rank[e] = atomicAdd(&g_cnt[dst[e]], 1);
    }
}

// ---------------------------------------------------------------------------
// Scan stage 1: per-segment sums
// ---------------------------------------------------------------------------
__global__ void __launch_bounds__(256) scan1_kernel(int N) {
    __shared__ int ssum[256];
    int t = threadIdx.x;
    int base = blockIdx.x * SEG + t * 4;
    int s = 0;
#pragma unroll
    for (int j = 0; j < 4; ++j) {
        int idx = base + j;
        if (idx < N) s += g_cnt[idx];
    }
    ssum[t] = s;
    __syncthreads();
#pragma unroll
    for (int off = 128; off > 0; off >>= 1) {
        if (t < off) ssum[t] += ssum[t + off];
        __syncthreads();
    }
    if (t == 0) g_bsum[blockIdx.x] = ssum[0];
}

// ---------------------------------------------------------------------------
// Scan stage 3 (scan2 folded in): every block scans segment sums locally.
// ---------------------------------------------------------------------------
__global__ void __launch_bounds__(256) scan3_kernel(int N, int E, int nseg) {
    __shared__ int ssum[256];
    __shared__ int sbs[MAXSEG];
    int t = threadIdx.x;

    if (t < MAXSEG) sbs[t] = (t < nseg) ? g_bsum[t] : 0;
    __syncthreads();
#pragma unroll
    for (int off = 1; off < MAXSEG; off <<= 1) {
        int x = 0;
        if (t < MAXSEG && t >= off) x = sbs[t - off];
        __syncthreads();
        if (t < MAXSEG) sbs[t] += x;
        __syncthreads();
    }
    int blockPrefix = (blockIdx.x == 0) ? 0 : sbs[blockIdx.x - 1];

    int base = blockIdx.x * SEG + t * 4;
    int c[4];
    int tsum = 0;
#pragma unroll
    for (int j = 0; j < 4; ++j) {
        int idx = base + j;
        c[j] = (idx < N) ? g_cnt[idx] : 0;
        tsum += c[j];
    }
    ssum[t] = tsum;
    __syncthreads();
#pragma unroll
    for (int off = 1; off < 256; off <<= 1) {
        int x = (t >= off) ? ssum[t - off] : 0;
        __syncthreads();
        ssum[t] += x;
        __syncthreads();
    }
    int excl = ssum[t] - tsum;
    int pos = blockPrefix + excl;
#pragma unroll
    for (int j = 0; j < 4; ++j) {
        int idx = base + j;
        if (idx < N) {
            g_off[idx] = pos;
            pos += c[j];
        }
    }
    if (blockIdx.x == 0 && t == 0) g_off[N] = E;
}

// ---------------------------------------------------------------------------
// Permute edges into CSR order — NO atomics: slot = g_off[dst] + rank[e].
// All loads coalesced; one scattered 8B store per edge. Re-zeroes g_cnt.
// ---------------------------------------------------------------------------
__global__ void permute_kernel(const int* __restrict__ src,
                               const int* __restrict__ dst,
                               const float* __restrict__ val, int E, int N) {
    int t = blockIdx.x * blockDim.x + threadIdx.x;
    if (t < N) g_cnt[t] = 0;

    int base = t * 4;
    if (base + 3 < E) {
        int4   s4 = *(const int4*)&src[base];
        int4   d4 = *(const int4*)&dst[base];
        float4 v4 = *(const float4*)&val[base];
        int4   r4 = *(const int4*)&g_rank[base];
        g_edge[g_off[d4.x] + r4.x] = make_int2(s4.x, __float_as_int(v4.x));
        g_edge[g_off[d4.y] + r4.y] = make_int2(s4.y, __float_as_int(v4.y));
        g_edge[g_off[d4.z] + r4.z] = make_int2(s4.z, __float_as_int(v4.z));
        g_edge[g_off[d4.w] + r4.w] = make_int2(s4.w, __float_as_int(v4.w));
    } else {
        for (int e = base; e < E; ++e) {
            g_edge[g_off[dst[e]] + g_rank[e]] =
                make_int2(src[e], __float_as_int(val[e]));
        }
    }
}

// ---------------------------------------------------------------------------
// bf16 pack helper: {lo, hi} fp32 -> bf16x2
// ---------------------------------------------------------------------------
__device__ __forceinline__ uint32_t pk2(float lo, float hi) {
    uint32_t r;
    asm("cvt.rn.bf16x2.f32 %0, %1, %2;" : "=r"(r) : "f"(hi), "f"(lo));
    return r;
}

// ---------------------------------------------------------------------------
// Gather + convert: one warp per node.
//   LE = sum_e val[e] * feats[src[e]]   (register accumulator)
//   a = LE + feats[node], e = LE * feats[node]
//   split a,e into bf16 hi/lo and store the node's row of the 4 tile parts.
// ---------------------------------------------------------------------------
__global__ void __launch_bounds__(256)
gather_kernel(const float* __restrict__ feats, int N) {
    int node = (blockIdx.x << 3) + (threadIdx.x >> 5);
    if (node >= N) return;
    int lane = threadIdx.x & 31;
    int start = g_off[node];
    int end = g_off[node + 1];

    float4 acc = make_float4(0.f, 0.f, 0.f, 0.f);
    for (int base = start; base < end; base += 32) {
        int n = end - base;
        if (n > 32) n = 32;
        int s = 0;
        float v = 0.f;
        if (lane < n) {
            int2 ev = g_edge[base + lane];
            s = ev.x;
            v = __int_as_float(ev.y);
        }
#pragma unroll 4
        for (int j = 0; j < n; ++j) {
            int sj = __shfl_sync(0xffffffff, s, j);
            float vj = __shfl_sync(0xffffffff, v, j);
            float4 f = *reinterpret_cast<const float4*>(
                &feats[(long long)sj * FDIM + lane * 4]);
            acc.x += vj * f.x;
            acc.y += vj * f.y;
            acc.z += vj * f.z;
            acc.w += vj * f.w;
        }
    }

    // Convert: a = LE + ft, e = LE * ft; split to bf16 hi/lo.
    float4 ft = *reinterpret_cast<const float4*>(
        &feats[(long long)node * FDIM + lane * 4]);
    float a0 = acc.x + ft.x, a1 = acc.y + ft.y;
    float a2 = acc.z + ft.z, a3 = acc.w + ft.w;
    float e0 = acc.x * ft.x, e1 = acc.y * ft.y;
    float e2 = acc.z * ft.z, e3 = acc.w * ft.w;

    uint32_t ah01 = pk2(a0, a1), ah23 = pk2(a2, a3);
    float ar0 = a0 - __uint_as_float(ah01 << 16);
    float ar1 = a1 - __uint_as_float(ah01 & 0xFFFF0000u);
    float ar2 = a2 - __uint_as_float(ah23 << 16);
    float ar3 = a3 - __uint_as_float(ah23 & 0xFFFF0000u);
    uint2 ahv = make_uint2(ah01, ah23);
    uint2 alv = make_uint2(pk2(ar0, ar1), pk2(ar2, ar3));

    uint32_t eh01 = pk2(e0, e1), eh23 = pk2(e2, e3);
    float er0 = e0 - __uint_as_float(eh01 << 16);
    float er1 = e1 - __uint_as_float(eh01 & 0xFFFF0000u);
    float er2 = e2 - __uint_as_float(eh23 << 16);
    float er3 = e3 - __uint_as_float(eh23 & 0xFFFF0000u);
    uint2 ehv = make_uint2(eh01, eh23);
    uint2 elv = make_uint2(pk2(er0, er1), pk2(er2, er3));

    // Store the node's row into its tile's 4 parts (coalesced 256B per part).
    size_t base = (size_t)(node >> 6) * TILE_U2 + (size_t)(node & 63) * ROW_U2 + lane;
    g_A[base + 0 * PART_U2] = ahv;
    g_A[base + 1 * PART_U2] = alv;
    g_A[base + 2 * PART_U2] = ehv;
    g_A[base + 3 * PART_U2] = elv;
}

// ---------------------------------------------------------------------------
// HMMA helper
// ---------------------------------------------------------------------------
__device__ __forceinline__ void mma16816(float* c, uint32_t a0, uint32_t a1,
                                         uint32_t a2, uint32_t a3,
                                         uint32_t b0, uint32_t b1) {
    asm volatile(
        "mma.sync.aligned.m16n8k16.row.col.f32.bf16.bf16.f32 "
        "{%0,%1,%2,%3}, {%4,%5,%6,%7}, {%8,%9}, {%0,%1,%2,%3};"
        : "+f"(c[0]), "+f"(c[1]), "+f"(c[2]), "+f"(c[3])
        : "r"(a0), "r"(a1), "r"(a2), "r"(a3), "r"(b0), "r"(b1));
}

// ---------------------------------------------------------------------------
// GEMM: tiles arrive pre-converted. Part-pair staged cp.async pipeline:
// ph0 reads {ah,al}, ph1 reads {eh,el}; each pair's copy is issued one
// phase ahead so its latency hides under a full MMA phase.
// Persistent, 1 CTA/SM, 256 threads (8 warps: 2x4 m/n grid), 64-row tiles.
// ---------------------------------------------------------------------------
#define OFF_A    0
#define OFF_W1H  69632
#define OFF_W1L  (OFF_W1H + 128 * WPAD * 2)
#define OFF_W2H  (OFF_W1L + 128 * WPAD * 2)
#define OFF_W2L  (OFF_W2H + 128 * WPAD * 2)
#define OFF_BIAS (OFF_W2L + 128 * WPAD * 2)
#define SMEM_TOTAL_MM (OFF_BIAS + 128 * 4)    // 209,920 B

#define CP_ASYNC16(sa, gp) \
    asm volatile("cp.async.cg.shared.global [%0], [%1], 16;" \
                 :: "r"(sa), "l"(gp))
#define CP_COMMIT() asm volatile("cp.async.commit_group;")
#define CP_WAIT1()  asm volatile("cp.async.wait_group 1;")
#define CP_WAIT0()  asm volatile("cp.async.wait_group 0;")

// Copy one part-pair (2176 granules of 16B) of tile T, pair P (0 or 1).
#define COPY_PAIR(T, P) do {                                                  \
        const uint2* gsrc_ = g_A + (size_t)(T) * TILE_U2 + (P) * PAIR_U2;     \
        uint32_t sdst_ = smem_u32 + OFF_A + (P) * (PAIR_U2 * 8);              \
        _Pragma("unroll")                                                     \
        for (int i_ = 0; i_ < 9; ++i_) {                                      \
            int g_ = tid + i_ * 256;                                          \
            if (g_ < PAIR_GRAN)                                               \
                CP_ASYNC16(sdst_ + g_ * 16, gsrc_ + (size_t)g_ * 2);          \
        }                                                                     \
        CP_COMMIT();                                                          \
    } while (0)

__global__ void __launch_bounds__(256, 1)
gemm_mm_kernel(const float* __restrict__ W1, const float* __restrict__ b1,
               const float* __restrict__ W2, const float* __restrict__ b2,
               float* __restrict__ out, int N, int nTiles) {
    extern __shared__ char smem[];
    uint32_t smem_u32;
    asm("{ .reg .u64 t; cvta.to.shared.u64 t, %1; cvt.u32.u64 %0, t; }"
        : "=r"(smem_u32) : "l"(smem));

    int tid = threadIdx.x;
    int wid = tid >> 5;
    int lane = tid & 31;
    int wm = wid & 1;        // 0..1 : 32-row slice
    int wn = wid >> 1;       // 0..3 : 32-col slice
    int grp = lane >> 2;     // 0..7
    int quad = lane & 3;     // 0..3

    // ---- one-time: split W1/W2 into bf16 hi/lo in smem; bias ----
    for (int i = tid; i < FDIM * FDIM; i += 256) {
        int n = i >> 7;
        int k = i & 127;
        float w1 = W1[i];
        float w2 = W2[i];
        uint32_t h1 = pk2(w1, 0.f) & 0xFFFFu;
        uint32_t h2 = pk2(w2, 0.f) & 0xFFFFu;
        float r1 = w1 - __uint_as_float(h1 << 16);
        float r2 = w2 - __uint_as_float(h2 << 16);
        uint32_t l1 = pk2(r1, 0.f) & 0xFFFFu;
        uint32_t l2 = pk2(r2, 0.f) & 0xFFFFu;
        size_t o = (size_t)(n * WPAD + k) * 2;
        *(uint16_t*)(smem + OFF_W1H + o) = (uint16_t)h1;
        *(uint16_t*)(smem + OFF_W1L + o) = (uint16_t)l1;
        *(uint16_t*)(smem + OFF_W2H + o) = (uint16_t)h2;
        *(uint16_t*)(smem + OFF_W2L + o) = (uint16_t)l2;
    }
    for (int i = tid; i < FDIM; i += 256)
        *(float*)(smem + OFF_BIAS + i * 4) = b1[i] + b2[i];
    __syncthreads();

    float bv[4][2];
#pragma unroll
    for (int j = 0; j < 4; ++j) {
        int col = wn * 32 + j * 8 + quad * 2;
        bv[j][0] = *(float*)(smem + OFF_BIAS + col * 4);
        bv[j][1] = *(float*)(smem + OFF_BIAS + (col + 1) * 4);
    }

    // ---- prologue: both part-pairs of the first tile in flight ----
    if (blockIdx.x < nTiles) {
        COPY_PAIR((int)blockIdx.x, 0);
        COPY_PAIR((int)blockIdx.x, 1);
    }

    for (int tile = blockIdx.x; tile < nTiles; tile += gridDim.x) {
        int row0 = tile << 6;
        int nxt = tile + (int)gridDim.x;
        bool has_next = nxt < nTiles;

        float acc[2][4][4];
#pragma unroll
        for (int mt = 0; mt < 2; ++mt)
#pragma unroll
            for (int nt = 0; nt < 4; ++nt)
#pragma unroll
                for (int f = 0; f < 4; ++f) acc[mt][nt][f] = 0.f;

        const int aoffH[2] = {OFF_A, OFF_A + 2 * PART_U2 * 8};
        const int aoffL[2] = {OFF_A + 1 * PART_U2 * 8, OFF_A + 3 * PART_U2 * 8};
        const int woffH[2] = {OFF_W1H, OFF_W2H};
        const int woffL[2] = {OFF_W1L, OFF_W2L};

#pragma unroll
        for (int ph = 0; ph < 2; ++ph) {
            if (ph == 0) {
                CP_WAIT1();
            } else {
                if (has_next) CP_WAIT1(); else CP_WAIT0();
            }
            __syncthreads();

            const char* sAH = smem + aoffH[ph];
            const char* sAL = smem + aoffL[ph];
            const char* sWH = smem + woffH[ph];
            const char* sWL = smem + woffL[ph];
#pragma unroll
            for (int ks = 0; ks < 8; ++ks) {
                int kb = ks * 16 + quad * 2;
                uint32_t bh[4][2], bl[4][2];
#pragma unroll
                for (int nt = 0; nt < 4; ++nt) {
                    int n = wn * 32 + nt * 8 + grp;
                    size_t o0 = (size_t)(n * WPAD + kb) * 2;
                    size_t o1 = (size_t)(n * WPAD + kb + 8) * 2;
                    bh[nt][0] = *(const uint32_t*)(sWH + o0);
                    bh[nt][1] = *(const uint32_t*)(sWH + o1);
                    bl[nt][0] = *(const uint32_t*)(sWL + o0);
                    bl[nt][1] = *(const uint32_t*)(sWL + o1);
                }
#pragma unroll
                for (int mt = 0; mt < 2; ++mt) {
                    int rA = wm * 32 + mt * 16 + grp;
                    size_t o0 = (size_t)(rA * APAD + kb) * 2;
                    size_t o1 = (size_t)((rA + 8) * APAD + kb) * 2;
                    size_t o2 = (size_t)(rA * APAD + kb + 8) * 2;
                    size_t o3 = (size_t)((rA + 8) * APAD + kb + 8) * 2;
                    uint32_t ah0 = *(const uint32_t*)(sAH + o0);
                    uint32_t ah1 = *(const uint32_t*)(sAH + o1);
                    uint32_t ah2 = *(const uint32_t*)(sAH + o2);
                    uint32_t ah3 = *(const uint32_t*)(sAH + o3);
                    uint32_t al0 = *(const uint32_t*)(sAL + o0);
                    uint32_t al1 = *(const uint32_t*)(sAL + o1);
                    uint32_t al2 = *(const uint32_t*)(sAL + o2);
                    uint32_t al3 = *(const uint32_t*)(sAL + o3);
#pragma unroll
                    for (int nt = 0; nt < 4; ++nt) {
                        mma16816(acc[mt][nt], ah0, ah1, ah2, ah3, bh[nt][0], bh[nt][1]);
                        mma16816(acc[mt][nt], al0, al1, al2, al3, bh[nt][0], bh[nt][1]);
                        mma16816(acc[mt][nt], ah0, ah1, ah2, ah3, bl[nt][0], bl[nt][1]);
                    }
                }
            }

            __syncthreads();
            if (has_next) COPY_PAIR(nxt, ph);
        }

        // ---- epilogue: acc + bias -> out ----
#pragma unroll
        for (int mt = 0; mt < 2; ++mt) {
            int r_lo = row0 + wm * 32 + mt * 16 + grp;
            int r_hi = r_lo + 8;
#pragma unroll
            for (int nt = 0; nt < 4; ++nt) {
                int col = wn * 32 + nt * 8 + quad * 2;
                if (r_lo < N) {
                    float2 o;
                    o.x = acc[mt][nt][0] + bv[nt][0];
                    o.y = acc[mt][nt][1] + bv[nt][1];
                    *(float2*)&out[(size_t)r_lo * FDIM + col] = o;
                }
                if (r_hi < N) {
                    float2 o;
                    o.x = acc[mt][nt][2] + bv[nt][0];
                    o.y = acc[mt][nt][3] + bv[nt][1];
                    *(float2*)&out[(size_t)r_hi * FDIM + col] = o;
                }
            }
        }
    }
}

// ---------------------------------------------------------------------------
extern "C" void kernel_launch(void* const* d_in, const int* in_sizes, int n_in,
                              void* d_out, int out_size) {
    const int*   src   = (const int*)d_in[0];
    const int*   dst   = (const int*)d_in[1];
    const float* val   = (const float*)d_in[2];
    const float* feats = (const float*)d_in[3];
    const float* W1    = (const float*)d_in[4];
    const float* b1    = (const float*)d_in[5];
    const float* W2    = (const float*)d_in[6];
    const float* b2    = (const float*)d_in[7];
    float* out = (float*)d_out;

    int E = in_sizes[0];
    int N = in_sizes[3] / FDIM;
    int nseg = (N + SEG - 1) / SEG;
    int nTiles = (N + 63) / 64;

    cudaFuncSetAttribute(gemm_mm_kernel,
                         cudaFuncAttributeMaxDynamicSharedMemorySize,
                         SMEM_TOTAL_MM);

    int e4 = (E + 3) / 4;   // threads for 4-edge kernels
    hist_kernel<<<(e4 + 255) / 256, 256>>>(dst, E);
    scan1_kernel<<<nseg, 256>>>(N);
    scan3_kernel<<<nseg, 256>>>(N, E, nseg);
    {
        // permute also zeroes g_cnt[0..N): need max(e4, N) threads
        int nthr = e4 > N ? e4 : N;
        permute_kernel<<<(nthr + 255) / 256, 256>>>(src, dst, val, E, N);
    }
    gather_kernel<<<(N + 7) / 8, 256>>>(feats, N);

    int grid = nTiles < 148 ? nTiles : 148;
    gemm_mm_kernel<<<grid, 256, SMEM_TOTAL_MM>>>(W1, b1, W2, b2, out,
                                                 N, nTiles);
}